// round 13
// baseline (speedup 1.0000x reference)
#include <cuda_runtime.h>
#include <cuda_fp16.h>
#include <cstdint>

// ---------------------------------------------------------------------------
// LongShortAttention  (B=4, N=4096, DIM=1024, H=16, DH=64, W=128, S=16, R=1)
// R12: rotary kernel deleted -> cos/sin table + in-kernel application inside
// attention (q regs, local-K smem pass) and gkv.  attention/gkv read
// qproj/kvproj directly.  dp chain split into 4 partials (ILP).
// GEMM (f16 ldmatrix) unchanged from R10/R11.
// ---------------------------------------------------------------------------

#define NROWS   16384          // B*N
#define SEQ     4096
#define NHEADS  16
#define DH      64
#define BHDIM   64             // B*HEADS
#define WIN     128
#define NWIN    32
#define NSEG    256

// -------------------- scratch (static device globals) ----------------------
__device__ float  g_qproj [(size_t)NROWS * 1024];
__device__ float  g_kvproj[(size_t)NROWS * 1024];
__device__ float  g_gkv   [(size_t)BHDIM * NSEG * DH];
__device__ float  g_rtab  [SEQ * 64];               // [n][0:32)=cos, [32:64)=sin
__device__ __half g_xh    [(size_t)NROWS * 1024];
__device__ __half g_wqh   [1024 * 1024];
__device__ __half g_wkvh  [1024 * 1024];
__device__ __half g_wouth [1024 * 1024];
__device__ __half g_aouth [(size_t)NROWS * 1024];   // [b][t][h*64+d]

// ------------------------------ helpers ------------------------------------
__device__ __forceinline__ void mma_f16(float* c, const uint32_t* a, const uint32_t* b) {
    asm volatile(
        "mma.sync.aligned.m16n8k16.row.col.f32.f16.f16.f32 "
        "{%0,%1,%2,%3}, {%4,%5,%6,%7}, {%8,%9}, {%0,%1,%2,%3};"
        : "+f"(c[0]), "+f"(c[1]), "+f"(c[2]), "+f"(c[3])
        : "r"(a[0]), "r"(a[1]), "r"(a[2]), "r"(a[3]), "r"(b[0]), "r"(b[1]));
}

__device__ __forceinline__ void ldm_x4(uint32_t* r, uint32_t addr) {
    asm volatile("ldmatrix.sync.aligned.m8n8.x4.shared.b16 {%0,%1,%2,%3}, [%4];"
        : "=r"(r[0]), "=r"(r[1]), "=r"(r[2]), "=r"(r[3]) : "r"(addr));
}

__device__ __forceinline__ void ldm_x4_t(uint32_t* r, uint32_t addr) {
    asm volatile("ldmatrix.sync.aligned.m8n8.x4.trans.shared.b16 {%0,%1,%2,%3}, [%4];"
        : "=r"(r[0]), "=r"(r[1]), "=r"(r[2]), "=r"(r[3]) : "r"(addr));
}

// ------------------------ fp32 -> fp16 conversion --------------------------
__global__ __launch_bounds__(256)
void cvt_f2h(const float* __restrict__ src, __half* __restrict__ dst, int n)
{
    int i = (blockIdx.x * blockDim.x + threadIdx.x) * 8;
    if (i >= n) return;
    float4 v0 = *(const float4*)(src + i);
    float4 v1 = *(const float4*)(src + i + 4);
    __half2 h0 = __floats2half2_rn(v0.x, v0.y);
    __half2 h1 = __floats2half2_rn(v0.z, v0.w);
    __half2 h2 = __floats2half2_rn(v1.x, v1.y);
    __half2 h3 = __floats2half2_rn(v1.z, v1.w);
    uint4 u;
    u.x = *(uint32_t*)&h0; u.y = *(uint32_t*)&h1;
    u.z = *(uint32_t*)&h2; u.w = *(uint32_t*)&h3;
    *(uint4*)(dst + i) = u;
}

// ------------------------ rotary cos/sin table -----------------------------
__global__ __launch_bounds__(256)
void rotgen_kernel(float* __restrict__ tab)
{
    int idx = blockIdx.x * blockDim.x + threadIdx.x;   // SEQ*32
    if (idx >= SEQ * 32) return;
    int n = idx >> 5, i = idx & 31;
    float invf  = __powf(10000.f, (-2.f / 64.f) * (float)i);
    float theta = (float)n * invf;
    float s, c;
    sincosf(theta, &s, &c);
    tab[n * 64 + i]      = c;
    tab[n * 64 + 32 + i] = s;
}

// --------------------------- f16 tiled GEMM (R10) --------------------------
#define A_STR 80
#define B_STR 272

__global__ __launch_bounds__(256, 2)
void gemm_f16ldm(const __half* __restrict__ A, const __half* __restrict__ B,
                 const float* __restrict__ bias, float* __restrict__ C,
                 int M, int N, int K)
{
    __shared__ __align__(16) char sA[128 * A_STR];   // 10240 B
    __shared__ __align__(16) char sB[32 * B_STR];    // 8704 B

    const int tid = threadIdx.x;
    const size_t bM = (size_t)blockIdx.y * 128;
    const size_t bN = (size_t)blockIdx.x * 128;

    const __half* Ab = A + bM * (size_t)K;
    const __half* Bb = B + bN;

    const int aRow = tid >> 2;
    const int aOff = tid & 3;
    const int bRow = tid >> 4;
    const int bOff = tid & 15;

    const int wid  = tid >> 5;
    const int lane = tid & 31;
    const int wm   = wid >> 2;
    const int wn   = wid & 3;
    const int mbase = wm * 64;
    const int nbase = wn * 32;
    const int g  = lane >> 2;
    const int tg = lane & 3;
    const int part = lane >> 3;
    const int r8   = lane & 7;

    const uint32_t sA32 = (uint32_t)__cvta_generic_to_shared(sA);
    const uint32_t sB32 = (uint32_t)__cvta_generic_to_shared(sB);

    float acc[4][4][4];
    #pragma unroll
    for (int mt = 0; mt < 4; mt++)
        #pragma unroll
        for (int nt = 0; nt < 4; nt++)
            #pragma unroll
            for (int r = 0; r < 4; r++) acc[mt][nt][r] = 0.f;

    uint4 pa0 = *(const uint4*)(Ab + (size_t)aRow        * K + aOff * 8);
    uint4 pa1 = *(const uint4*)(Ab + (size_t)(aRow + 64) * K + aOff * 8);
    uint4 pb0 = *(const uint4*)(Bb + (size_t)bRow        * N + bOff * 8);
    uint4 pb1 = *(const uint4*)(Bb + (size_t)(bRow + 16) * N + bOff * 8);

    const int nKT = K / 32;
    for (int kt = 0; kt < nKT; kt++) {
        *(uint4*)(sA + aRow        * A_STR + aOff * 16) = pa0;
        *(uint4*)(sA + (aRow + 64) * A_STR + aOff * 16) = pa1;
        *(uint4*)(sB + bRow        * B_STR + bOff * 16) = pb0;
        *(uint4*)(sB + (bRow + 16) * B_STR + bOff * 16) = pb1;
        __syncthreads();

        if (kt + 1 < nKT) {
            const int k0 = (kt + 1) * 32;
            pa0 = *(const uint4*)(Ab + (size_t)aRow        * K + k0 + aOff * 8);
            pa1 = *(const uint4*)(Ab + (size_t)(aRow + 64) * K + k0 + aOff * 8);
            pb0 = *(const uint4*)(Bb + (size_t)(k0 + bRow)      * N + bOff * 8);
            pb1 = *(const uint4*)(Bb + (size_t)(k0 + bRow + 16) * N + bOff * 8);
        }

        #pragma unroll
        for (int ks = 0; ks < 2; ks++) {
            uint32_t afr[4][4], bfr[4][2];
            #pragma unroll
            for (int mt = 0; mt < 4; mt++) {
                const int row = mbase + mt * 16 + r8 + (part & 1) * 8;
                const uint32_t byte = (uint32_t)(ks * 32 + (part >> 1) * 16);
                ldm_x4(afr[mt], sA32 + row * A_STR + byte);
            }
            #pragma unroll
            for (int np = 0; np < 2; np++) {
                uint32_t t[4];
                const int row = ks * 16 + r8 + (part & 1) * 8;
                const uint32_t byte = (uint32_t)((nbase + np * 16) * 2 + (part >> 1) * 16);
                ldm_x4_t(t, sB32 + row * B_STR + byte);
                bfr[2 * np][0]     = t[0];
                bfr[2 * np][1]     = t[1];
                bfr[2 * np + 1][0] = t[2];
                bfr[2 * np + 1][1] = t[3];
            }
            #pragma unroll
            for (int mt = 0; mt < 4; mt++)
                #pragma unroll
                for (int nt = 0; nt < 4; nt++)
                    mma_f16(acc[mt][nt], afr[mt], bfr[nt]);
        }
        __syncthreads();
    }

    #pragma unroll
    for (int mt = 0; mt < 4; mt++) {
        const size_t row0 = bM + mbase + mt * 16 + g;
        #pragma unroll
        for (int nt = 0; nt < 4; nt++) {
            const size_t col = bN + nbase + nt * 8 + tg * 2;
            float bz0 = 0.f, bz1 = 0.f;
            if (bias) { bz0 = bias[col]; bz1 = bias[col + 1]; }
            float2 v0 = make_float2(acc[mt][nt][0] + bz0, acc[mt][nt][1] + bz1);
            float2 v1 = make_float2(acc[mt][nt][2] + bz0, acc[mt][nt][3] + bz1);
            *(float2*)(C + row0 * (size_t)N + col)       = v0;
            *(float2*)(C + (row0 + 8) * (size_t)N + col) = v1;
        }
    }
}

// ------------------------- global kv aggregation ---------------------------
// reads kvproj [b][n][h*64+d]; applies rotary in smem via table.
__global__ __launch_bounds__(32)
void gkv_kernel(const float* __restrict__ kvp, const float* __restrict__ tab,
                const float* __restrict__ Wproj,
                const float* __restrict__ gg, const float* __restrict__ gb,
                float* __restrict__ gkv)
{
    __shared__ float skv[16 * 68];
    __shared__ float swp[64];
    __shared__ float slog[16];

    const int seg  = blockIdx.x;
    const int bh   = blockIdx.y;
    const int lane = threadIdx.x;
    const int b    = bh >> 4, h = bh & 15;

    const float* base = kvp + ((size_t)(b * SEQ + seg * 16)) * 1024 + h * 64;
    for (int i = lane; i < 256; i += 32) {
        int s = i >> 4, d4 = (i & 15) << 2;
        *(float4*)&skv[s * 68 + d4] = *(const float4*)(base + (size_t)s * 1024 + d4);
    }
    if (lane < 16) *(float4*)&swp[lane * 4] = *(const float4*)(Wproj + lane * 4);
    __syncwarp();

    // rotary in smem: lane owns dim pair (lane, lane+32) of every row
    #pragma unroll
    for (int s = 0; s < 16; s++) {
        const float* tr = tab + (size_t)(seg * 16 + s) * 64;
        float c = tr[lane], sn = tr[32 + lane];
        float v0 = skv[s * 68 + lane], v1 = skv[s * 68 + lane + 32];
        skv[s * 68 + lane]      = v0 * c - v1 * sn;
        skv[s * 68 + lane + 32] = v1 * c + v0 * sn;
    }
    __syncwarp();

    if (lane < 16) {
        float a = 0.f;
        #pragma unroll
        for (int d = 0; d < 64; d++) a += skv[lane * 68 + d] * swp[d];
        slog[lane] = a;
    }
    __syncwarp();

    float mx = -1e30f;
    #pragma unroll
    for (int s = 0; s < 16; s++) mx = fmaxf(mx, slog[s]);
    float se = 0.f;
    #pragma unroll
    for (int s = 0; s < 16; s++) se += __expf(slog[s] - mx);
    float inv = 1.f / se;

    float g0 = 0.f, g1 = 0.f;
    #pragma unroll
    for (int s = 0; s < 16; s++) {
        float ps = __expf(slog[s] - mx) * inv;
        g0 += ps * skv[s * 68 + lane];
        g1 += ps * skv[s * 68 + lane + 32];
    }

    float sum = g0 + g1, sq = g0 * g0 + g1 * g1;
    #pragma unroll
    for (int o = 16; o; o >>= 1) {
        sum += __shfl_xor_sync(0xffffffffu, sum, o);
        sq  += __shfl_xor_sync(0xffffffffu, sq, o);
    }
    float mean = sum * (1.f / 64.f);
    float var  = sq * (1.f / 64.f) - mean * mean;
    float rstd = rsqrtf(var + 1e-5f);

    float* outp = gkv + ((size_t)bh * NSEG + seg) * 64;
    outp[lane]      = (g0 - mean) * rstd * gg[lane]      + gb[lane];
    outp[lane + 32] = (g1 - mean) * rstd * gg[lane + 32] + gb[lane + 32];
}

// ------------------------------ attention ----------------------------------
// Two-phase (R11).  Reads qproj/kvproj directly; rotary applied on load via
// table.  dp split into 4 partial chains for ILP.
#define KSTRIDE 68
#define FMAX 16.0f

__global__ __launch_bounds__(512, 2)
void attn_kernel(const float* __restrict__ qp_, const float* __restrict__ kvp,
                 const float* __restrict__ tab,
                 const float* __restrict__ gkv, const float* __restrict__ lng_,
                 const float* __restrict__ lnb_, __half* __restrict__ out)
{
    extern __shared__ float keys[];     // [256][KSTRIDE]
    __shared__ float s_lng[64], s_lnb[64];

    const int w   = blockIdx.x;
    const int bh  = blockIdx.y;
    const int tid = threadIdx.x;
    const int b   = bh >> 4, h = bh & 15;

    if (tid < 64)  { s_lng[tid] = lng_[tid]; s_lnb[tid] = lnb_[tid]; }

    const int row  = tid >> 2;
    const int quad = tid & 3;
    const int t    = w * WIN + row;
    const int d0   = quad * 16;

    const int warpid  = tid >> 5;
    const int rowMaxW = warpid * 8 + 7;

    // ---- q load + rotary + scale (own chunk d0, partner chunk d0^32) ----
    float qr[16];
    {
        const float* qrow = qp_ + ((size_t)(b * SEQ + t)) * 1024 + h * 64;
        float own[16], part[16];
        #pragma unroll
        for (int m = 0; m < 4; m++) {
            *(float4*)&own[m * 4]  = *(const float4*)(qrow + d0 + m * 4);
            *(float4*)&part[m * 4] = *(const float4*)(qrow + (d0 ^ 32) + m * 4);
        }
        const float* tr = tab + (size_t)t * 64;
        const float SC = 0.125f;
        #pragma unroll
        for (int m = 0; m < 16; m++) {
            int d = d0 + m, i = d & 31;
            float c = tr[i], sn = tr[32 + i];
            qr[m] = (d < 32) ? (own[m] * c - part[m] * sn) * SC
                             : (own[m] * c + part[m] * sn) * SC;
        }
    }

    float acc[16];
    #pragma unroll
    for (int d = 0; d < 16; d++) acc[d] = 0.f;
    float l = 0.f;

    // ======================= phase A: global keys =========================
    {
        const float* gbase = gkv + (size_t)bh * NSEG * 64;
        for (int idx = tid; idx < 4096; idx += 512) {
            int j = idx >> 4, d4 = (idx & 15) << 2;
            *(float4*)&keys[j * KSTRIDE + d4] = *(const float4*)(gbase + j * 64 + d4);
        }
        __syncthreads();

        const int nglobal = t >> 4;
        const int gLimW   = min(NSEG, (w * WIN + rowMaxW) >> 4);

        #pragma unroll 2
        for (int j = 0; j < gLimW; j++) {
            const float* kp2 = &keys[j * KSTRIDE + d0];
            float kr[16];
            *(float4*)&kr[0]  = *(const float4*)(kp2);
            *(float4*)&kr[4]  = *(const float4*)(kp2 + 4);
            *(float4*)&kr[8]  = *(const float4*)(kp2 + 8);
            *(float4*)&kr[12] = *(const float4*)(kp2 + 12);
            float dp0 = 0.f, dp1 = 0.f, dp2 = 0.f, dp3 = 0.f;
            #pragma unroll
            for (int d = 0; d < 4; d++) {
                dp0 += kr[d]      * qr[d];
                dp1 += kr[d + 4]  * qr[d + 4];
                dp2 += kr[d + 8]  * qr[d + 8];
                dp3 += kr[d + 12] * qr[d + 12];
            }
            float dp = (dp0 + dp1) + (dp2 + dp3);
            dp += __shfl_xor_sync(0xffffffffu, dp, 1);
            dp += __shfl_xor_sync(0xffffffffu, dp, 2);
            if (j < nglobal) {
                float p2 = __expf(dp - FMAX);
                l += p2;
                #pragma unroll
                for (int d = 0; d < 16; d++) acc[d] += p2 * kr[d];
            }
        }
        __syncthreads();   // everyone done reading global keys
    }

    // ======================= phase B: local keys ==========================
    {
        const int pos0 = (w - 1) * WIN;
        for (int idx = tid; idx < 4096; idx += 512) {
            int jj = idx >> 4, d4 = (idx & 15) << 2;
            int pos = pos0 + jj;
            float4 v = make_float4(0.f, 0.f, 0.f, 0.f);
            if (pos >= 0)
                v = *(const float4*)(kvp + ((size_t)(b * SEQ + pos)) * 1024
                                         + h * 64 + d4);
            *(float4*)&keys[jj * KSTRIDE + d4] = v;
        }
        __syncthreads();

        // rotary + layernorm per local row
        if (tid < 256) {
            int jj = tid;
            int pos = pos0 + jj;
            if (pos >= 0) {
                float* rowp = &keys[jj * KSTRIDE];
                const float* tr = tab + (size_t)pos * 64;
                float sum = 0.f, sq = 0.f;
                #pragma unroll
                for (int d = 0; d < 32; d++) {
                    float c = tr[d], sn = tr[32 + d];
                    float v0 = rowp[d], v1 = rowp[d + 32];
                    float r0 = v0 * c - v1 * sn;
                    float r1 = v1 * c + v0 * sn;
                    rowp[d]      = r0;
                    rowp[d + 32] = r1;
                    sum += r0 + r1;
                    sq  += r0 * r0 + r1 * r1;
                }
                float mean = sum * (1.f / 64.f);
                float var  = sq * (1.f / 64.f) - mean * mean;
                float rstd = rsqrtf(var + 1e-5f);
                #pragma unroll
                for (int d = 0; d < 64; d++)
                    rowp[d] = (rowp[d] - mean) * rstd * s_lng[d] + s_lnb[d];
            }
        }
        __syncthreads();

        const int locmax  = 128 + row;
        const int locmin  = (w == 0) ? 128 : 0;
        const int locMaxW = 128 + rowMaxW;

        #pragma unroll 2
        for (int jj = locmin; jj <= locMaxW; jj++) {
            const float* kp2 = &keys[jj * KSTRIDE + d0];
            float kr[16];
            *(float4*)&kr[0]  = *(const float4*)(kp2);
            *(float4*)&kr[4]  = *(const float4*)(kp2 + 4);
            *(float4*)&kr[8]  = *(const float4*)(kp2 + 8);
            *(float4*)&kr[12] = *(const float4*)(kp2 + 12);
            float dp0 = 0.f, dp1 = 0.f, dp2 = 0.f, dp3 = 0.f;
            #pragma unroll
            for (int d = 0; d < 4; d++) {
                dp0 += kr[d]      * qr[d];
                dp1 += kr[d + 4]  * qr[d + 4];
                dp2 += kr[d + 8]  * qr[d + 8];
                dp3 += kr[d + 12] * qr[d + 12];
            }
            float dp = (dp0 + dp1) + (dp2 + dp3);
            dp += __shfl_xor_sync(0xffffffffu, dp, 1);
            dp += __shfl_xor_sync(0xffffffffu, dp, 2);
            if (jj <= locmax) {
                float p2 = __expf(dp - FMAX);
                l += p2;
                #pragma unroll
                for (int d = 0; d < 16; d++) acc[d] += p2 * kr[d];
            }
        }
    }

    float inv = 1.f / l;
    __half* op = out + ((size_t)b * SEQ + t) * 1024 + h * 64 + d0;
    uint32_t o[8];
    #pragma unroll
    for (int m = 0; m < 8; m++) {
        __half2 hh = __floats2half2_rn(acc[2 * m] * inv, acc[2 * m + 1] * inv);
        o[m] = *(uint32_t*)&hh;
    }
    *(uint4*)(op)     = make_uint4(o[0], o[1], o[2], o[3]);
    *(uint4*)(op + 8) = make_uint4(o[4], o[5], o[6], o[7]);
}

// ------------------------------ launcher -----------------------------------
extern "C" void kernel_launch(void* const* d_in, const int* in_sizes, int n_in,
                              void* d_out, int out_size)
{
    const float* x     = (const float*)d_in[0];
    const float* Wq    = (const float*)d_in[1];
    const float* Wkv   = (const float*)d_in[2];
    const float* Wproj = (const float*)d_in[3];
    const float* Wout  = (const float*)d_in[4];
    const float* bout  = (const float*)d_in[5];
    const float* lng   = (const float*)d_in[6];
    const float* lnb   = (const float*)d_in[7];
    const float* gng   = (const float*)d_in[8];
    const float* gnb   = (const float*)d_in[9];
    float* out = (float*)d_out;

    float *qproj, *kvproj, *gkvb, *rtab;
    __half *xh, *wqh, *wkvh, *wouth, *aouth;
    cudaGetSymbolAddress((void**)&qproj,  g_qproj);
    cudaGetSymbolAddress((void**)&kvproj, g_kvproj);
    cudaGetSymbolAddress((void**)&gkvb,   g_gkv);
    cudaGetSymbolAddress((void**)&rtab,   g_rtab);
    cudaGetSymbolAddress((void**)&xh,     g_xh);
    cudaGetSymbolAddress((void**)&wqh,    g_wqh);
    cudaGetSymbolAddress((void**)&wkvh,   g_wkvh);
    cudaGetSymbolAddress((void**)&wouth,  g_wouth);
    cudaGetSymbolAddress((void**)&aouth,  g_aouth);

    const int nx = NROWS * 1024, nw = 1024 * 1024;
    cvt_f2h<<<nx / (256 * 8), 256>>>(x,    xh,    nx);
    cvt_f2h<<<nw / (256 * 8), 256>>>(Wq,   wqh,   nw);
    cvt_f2h<<<nw / (256 * 8), 256>>>(Wkv,  wkvh,  nw);
    cvt_f2h<<<nw / (256 * 8), 256>>>(Wout, wouth, nw);
    rotgen_kernel<<<(SEQ * 32) / 256, 256>>>(rtab);

    dim3 gg1(1024 / 128, NROWS / 128);     // (8, 128)
    gemm_f16ldm<<<gg1, 256>>>(xh, wqh,  nullptr, qproj,  NROWS, 1024, 1024);
    gemm_f16ldm<<<gg1, 256>>>(xh, wkvh, nullptr, kvproj, NROWS, 1024, 1024);

    gkv_kernel<<<dim3(NSEG, BHDIM), 32>>>(kvproj, rtab, Wproj, gng, gnb, gkvb);

    int smem = 256 * KSTRIDE * sizeof(float);   // 69632 B
    cudaFuncSetAttribute(attn_kernel, cudaFuncAttributeMaxDynamicSharedMemorySize, smem);
    attn_kernel<<<dim3(NWIN, BHDIM), 512, smem>>>(qproj, kvproj, rtab, gkvb,
                                                  lng, lnb, aouth);

    gemm_f16ldm<<<gg1, 256>>>(aouth, wouth, bout, out, NROWS, 1024, 1024);
}

// round 16
// speedup vs baseline: 1.0749x; 1.0749x over previous
#include <cuda_runtime.h>
#include <cuda_fp16.h>
#include <cstdint>

// ---------------------------------------------------------------------------
// LongShortAttention  (B=4, N=4096, DIM=1024, H=16, DH=64, W=128, S=16, R=1)
// R15: R11 pipeline + dp split into 2 partial chains (reshaped from the
// R13/R14 4-way split that coincided with container failures).
// ---------------------------------------------------------------------------

#define NROWS   16384          // B*N
#define SEQ     4096
#define NHEADS  16
#define DH      64
#define BHDIM   64             // B*HEADS
#define WIN     128
#define NWIN    32
#define NSEG    256

// -------------------- scratch (static device globals) ----------------------
__device__ float  g_qproj [(size_t)NROWS * 1024];
__device__ float  g_kvproj[(size_t)NROWS * 1024];
__device__ float  g_q     [(size_t)NROWS * 1024];   // [bh][n][64]
__device__ float  g_kv    [(size_t)NROWS * 1024];   // [bh][n][64]
__device__ float  g_gkv   [(size_t)BHDIM * NSEG * DH];
__device__ __half g_xh    [(size_t)NROWS * 1024];
__device__ __half g_wqh   [1024 * 1024];
__device__ __half g_wkvh  [1024 * 1024];
__device__ __half g_wouth [1024 * 1024];
__device__ __half g_aouth [(size_t)NROWS * 1024];   // [b][t][h*64+d]

// ------------------------------ helpers ------------------------------------
__device__ __forceinline__ void mma_f16(float* c, const uint32_t* a, const uint32_t* b) {
    asm volatile(
        "mma.sync.aligned.m16n8k16.row.col.f32.f16.f16.f32 "
        "{%0,%1,%2,%3}, {%4,%5,%6,%7}, {%8,%9}, {%0,%1,%2,%3};"
        : "+f"(c[0]), "+f"(c[1]), "+f"(c[2]), "+f"(c[3])
        : "r"(a[0]), "r"(a[1]), "r"(a[2]), "r"(a[3]), "r"(b[0]), "r"(b[1]));
}

__device__ __forceinline__ void ldm_x4(uint32_t* r, uint32_t addr) {
    asm volatile("ldmatrix.sync.aligned.m8n8.x4.shared.b16 {%0,%1,%2,%3}, [%4];"
        : "=r"(r[0]), "=r"(r[1]), "=r"(r[2]), "=r"(r[3]) : "r"(addr));
}

__device__ __forceinline__ void ldm_x4_t(uint32_t* r, uint32_t addr) {
    asm volatile("ldmatrix.sync.aligned.m8n8.x4.trans.shared.b16 {%0,%1,%2,%3}, [%4];"
        : "=r"(r[0]), "=r"(r[1]), "=r"(r[2]), "=r"(r[3]) : "r"(addr));
}

// ------------------------ fp32 -> fp16 conversion --------------------------
__global__ __launch_bounds__(256)
void cvt_f2h(const float* __restrict__ src, __half* __restrict__ dst, int n)
{
    int i = (blockIdx.x * blockDim.x + threadIdx.x) * 8;
    if (i >= n) return;
    float4 v0 = *(const float4*)(src + i);
    float4 v1 = *(const float4*)(src + i + 4);
    __half2 h0 = __floats2half2_rn(v0.x, v0.y);
    __half2 h1 = __floats2half2_rn(v0.z, v0.w);
    __half2 h2 = __floats2half2_rn(v1.x, v1.y);
    __half2 h3 = __floats2half2_rn(v1.z, v1.w);
    uint4 u;
    u.x = *(uint32_t*)&h0; u.y = *(uint32_t*)&h1;
    u.z = *(uint32_t*)&h2; u.w = *(uint32_t*)&h3;
    *(uint4*)(dst + i) = u;
}

// --------------------------- f16 tiled GEMM (R10) --------------------------
#define A_STR 80
#define B_STR 272

__global__ __launch_bounds__(256, 2)
void gemm_f16ldm(const __half* __restrict__ A, const __half* __restrict__ B,
                 const float* __restrict__ bias, float* __restrict__ C,
                 int M, int N, int K)
{
    __shared__ __align__(16) char sA[128 * A_STR];   // 10240 B
    __shared__ __align__(16) char sB[32 * B_STR];    // 8704 B

    const int tid = threadIdx.x;
    const size_t bM = (size_t)blockIdx.y * 128;
    const size_t bN = (size_t)blockIdx.x * 128;

    const __half* Ab = A + bM * (size_t)K;
    const __half* Bb = B + bN;

    const int aRow = tid >> 2;
    const int aOff = tid & 3;
    const int bRow = tid >> 4;
    const int bOff = tid & 15;

    const int wid  = tid >> 5;
    const int lane = tid & 31;
    const int wm   = wid >> 2;
    const int wn   = wid & 3;
    const int mbase = wm * 64;
    const int nbase = wn * 32;
    const int g  = lane >> 2;
    const int tg = lane & 3;
    const int part = lane >> 3;
    const int r8   = lane & 7;

    const uint32_t sA32 = (uint32_t)__cvta_generic_to_shared(sA);
    const uint32_t sB32 = (uint32_t)__cvta_generic_to_shared(sB);

    float acc[4][4][4];
    #pragma unroll
    for (int mt = 0; mt < 4; mt++)
        #pragma unroll
        for (int nt = 0; nt < 4; nt++)
            #pragma unroll
            for (int r = 0; r < 4; r++) acc[mt][nt][r] = 0.f;

    uint4 pa0 = *(const uint4*)(Ab + (size_t)aRow        * K + aOff * 8);
    uint4 pa1 = *(const uint4*)(Ab + (size_t)(aRow + 64) * K + aOff * 8);
    uint4 pb0 = *(const uint4*)(Bb + (size_t)bRow        * N + bOff * 8);
    uint4 pb1 = *(const uint4*)(Bb + (size_t)(bRow + 16) * N + bOff * 8);

    const int nKT = K / 32;
    for (int kt = 0; kt < nKT; kt++) {
        *(uint4*)(sA + aRow        * A_STR + aOff * 16) = pa0;
        *(uint4*)(sA + (aRow + 64) * A_STR + aOff * 16) = pa1;
        *(uint4*)(sB + bRow        * B_STR + bOff * 16) = pb0;
        *(uint4*)(sB + (bRow + 16) * B_STR + bOff * 16) = pb1;
        __syncthreads();

        if (kt + 1 < nKT) {
            const int k0 = (kt + 1) * 32;
            pa0 = *(const uint4*)(Ab + (size_t)aRow        * K + k0 + aOff * 8);
            pa1 = *(const uint4*)(Ab + (size_t)(aRow + 64) * K + k0 + aOff * 8);
            pb0 = *(const uint4*)(Bb + (size_t)(k0 + bRow)      * N + bOff * 8);
            pb1 = *(const uint4*)(Bb + (size_t)(k0 + bRow + 16) * N + bOff * 8);
        }

        #pragma unroll
        for (int ks = 0; ks < 2; ks++) {
            uint32_t afr[4][4], bfr[4][2];
            #pragma unroll
            for (int mt = 0; mt < 4; mt++) {
                const int row = mbase + mt * 16 + r8 + (part & 1) * 8;
                const uint32_t byte = (uint32_t)(ks * 32 + (part >> 1) * 16);
                ldm_x4(afr[mt], sA32 + row * A_STR + byte);
            }
            #pragma unroll
            for (int np = 0; np < 2; np++) {
                uint32_t t[4];
                const int row = ks * 16 + r8 + (part & 1) * 8;
                const uint32_t byte = (uint32_t)((nbase + np * 16) * 2 + (part >> 1) * 16);
                ldm_x4_t(t, sB32 + row * B_STR + byte);
                bfr[2 * np][0]     = t[0];
                bfr[2 * np][1]     = t[1];
                bfr[2 * np + 1][0] = t[2];
                bfr[2 * np + 1][1] = t[3];
            }
            #pragma unroll
            for (int mt = 0; mt < 4; mt++)
                #pragma unroll
                for (int nt = 0; nt < 4; nt++)
                    mma_f16(acc[mt][nt], afr[mt], bfr[nt]);
        }
        __syncthreads();
    }

    #pragma unroll
    for (int mt = 0; mt < 4; mt++) {
        const size_t row0 = bM + mbase + mt * 16 + g;
        #pragma unroll
        for (int nt = 0; nt < 4; nt++) {
            const size_t col = bN + nbase + nt * 8 + tg * 2;
            float bz0 = 0.f, bz1 = 0.f;
            if (bias) { bz0 = bias[col]; bz1 = bias[col + 1]; }
            float2 v0 = make_float2(acc[mt][nt][0] + bz0, acc[mt][nt][1] + bz1);
            float2 v1 = make_float2(acc[mt][nt][2] + bz0, acc[mt][nt][3] + bz1);
            *(float2*)(C + row0 * (size_t)N + col)       = v0;
            *(float2*)(C + (row0 + 8) * (size_t)N + col) = v1;
        }
    }
}

// ------------------------------- rotary ------------------------------------
__global__ __launch_bounds__(256)
void rotary_kernel(const float* __restrict__ qp, const float* __restrict__ kp,
                   float* __restrict__ qo, float* __restrict__ ko)
{
    int idx = blockIdx.x * blockDim.x + threadIdx.x;
    if (idx >= NROWS * 512) return;
    int r = idx >> 9;
    int p = idx & 511;
    int h = p >> 5;
    int i = p & 31;
    int n = r & (SEQ - 1);
    int b = r >> 12;

    float invf  = __powf(10000.f, (-2.f / 64.f) * (float)i);
    float theta = (float)n * invf;
    float s, c;
    sincosf(theta, &s, &c);

    size_t src = (size_t)r * 1024 + h * 64 + i;
    float q0 = qp[src], q1 = qp[src + 32];
    float k0 = kp[src], k1 = kp[src + 32];

    size_t dst = (((size_t)(b * NHEADS + h)) * SEQ + n) * 64 + i;
    const float SC = 0.125f;
    qo[dst]      = (q0 * c - q1 * s) * SC;
    qo[dst + 32] = (q1 * c + q0 * s) * SC;
    ko[dst]      = k0 * c - k1 * s;
    ko[dst + 32] = k1 * c + k0 * s;
}

// ------------------------- global kv aggregation ---------------------------
__global__ __launch_bounds__(32)
void gkv_kernel(const float* __restrict__ kv, const float* __restrict__ Wproj,
                const float* __restrict__ gg, const float* __restrict__ gb,
                float* __restrict__ gkv)
{
    __shared__ float skv[16 * 68];
    __shared__ float swp[64];
    __shared__ float slog[16];

    const int seg  = blockIdx.x;
    const int bh   = blockIdx.y;
    const int lane = threadIdx.x;

    const float* base = kv + ((size_t)bh * SEQ + seg * 16) * 64;
    for (int i = lane; i < 256; i += 32) {
        int s = i >> 4, d4 = (i & 15) << 2;
        *(float4*)&skv[s * 68 + d4] = *(const float4*)(base + s * 64 + d4);
    }
    if (lane < 16) *(float4*)&swp[lane * 4] = *(const float4*)(Wproj + lane * 4);
    __syncwarp();

    if (lane < 16) {
        float a = 0.f;
        #pragma unroll
        for (int d = 0; d < 64; d++) a += skv[lane * 68 + d] * swp[d];
        slog[lane] = a;
    }
    __syncwarp();

    float mx = -1e30f;
    #pragma unroll
    for (int s = 0; s < 16; s++) mx = fmaxf(mx, slog[s]);
    float se = 0.f;
    #pragma unroll
    for (int s = 0; s < 16; s++) se += __expf(slog[s] - mx);
    float inv = 1.f / se;

    float g0 = 0.f, g1 = 0.f;
    #pragma unroll
    for (int s = 0; s < 16; s++) {
        float ps = __expf(slog[s] - mx) * inv;
        g0 += ps * skv[s * 68 + lane];
        g1 += ps * skv[s * 68 + lane + 32];
    }

    float sum = g0 + g1, sq = g0 * g0 + g1 * g1;
    #pragma unroll
    for (int o = 16; o; o >>= 1) {
        sum += __shfl_xor_sync(0xffffffffu, sum, o);
        sq  += __shfl_xor_sync(0xffffffffu, sq, o);
    }
    float mean = sum * (1.f / 64.f);
    float var  = sq * (1.f / 64.f) - mean * mean;
    float rstd = rsqrtf(var + 1e-5f);

    float* outp = gkv + ((size_t)bh * NSEG + seg) * 64;
    outp[lane]      = (g0 - mean) * rstd * gg[lane]      + gb[lane];
    outp[lane + 32] = (g1 - mean) * rstd * gg[lane + 32] + gb[lane + 32];
}

// ------------------------------ attention ----------------------------------
// Two-phase (R11).  dp computed with 2 partial chains (ILP reshape of the
// R13 4-way split).
#define KSTRIDE 68
#define FMAX 16.0f

__global__ __launch_bounds__(512, 2)
void attn_kernel(const float* __restrict__ q, const float* __restrict__ kv,
                 const float* __restrict__ gkv, const float* __restrict__ lng_,
                 const float* __restrict__ lnb_, __half* __restrict__ out)
{
    extern __shared__ float keys[];     // [256][KSTRIDE]
    __shared__ float s_lng[64], s_lnb[64];

    const int w   = blockIdx.x;
    const int bh  = blockIdx.y;
    const int tid = threadIdx.x;

    if (tid < 64)  { s_lng[tid] = lng_[tid]; s_lnb[tid] = lnb_[tid]; }

    const int row  = tid >> 2;
    const int quad = tid & 3;
    const int t    = w * WIN + row;
    const int d0   = quad * 16;

    const int warpid  = tid >> 5;
    const int rowMaxW = warpid * 8 + 7;

    float qr[16], acc[16];
    const float* qp = q + ((size_t)bh * SEQ + t) * 64 + d0;
    #pragma unroll
    for (int m = 0; m < 4; m++) *(float4*)&qr[m * 4] = *(const float4*)(qp + m * 4);
    #pragma unroll
    for (int d = 0; d < 16; d++) acc[d] = 0.f;
    float l = 0.f;

    // ======================= phase A: global keys =========================
    {
        const float* gbase = gkv + (size_t)bh * NSEG * 64;
        for (int idx = tid; idx < 4096; idx += 512) {
            int j = idx >> 4, d4 = (idx & 15) << 2;
            *(float4*)&keys[j * KSTRIDE + d4] = *(const float4*)(gbase + j * 64 + d4);
        }
        __syncthreads();

        const int nglobal = t >> 4;
        const int gLimW   = min(NSEG, (w * WIN + rowMaxW) >> 4);

        #pragma unroll 2
        for (int j = 0; j < gLimW; j++) {
            const float* kp2 = &keys[j * KSTRIDE + d0];
            float kr[16];
            *(float4*)&kr[0]  = *(const float4*)(kp2);
            *(float4*)&kr[4]  = *(const float4*)(kp2 + 4);
            *(float4*)&kr[8]  = *(const float4*)(kp2 + 8);
            *(float4*)&kr[12] = *(const float4*)(kp2 + 12);
            float dpa = 0.f, dpb = 0.f;
            #pragma unroll
            for (int d = 0; d < 8; d++) {
                dpa += kr[d]     * qr[d];
                dpb += kr[d + 8] * qr[d + 8];
            }
            float dp = dpa + dpb;
            dp += __shfl_xor_sync(0xffffffffu, dp, 1);
            dp += __shfl_xor_sync(0xffffffffu, dp, 2);
            if (j < nglobal) {
                float p2 = __expf(dp - FMAX);
                l += p2;
                #pragma unroll
                for (int d = 0; d < 16; d++) acc[d] += p2 * kr[d];
            }
        }
        __syncthreads();   // everyone done reading global keys
    }

    // ======================= phase B: local keys ==========================
    {
        const int pos0 = (w - 1) * WIN;
        const float* kbase = kv + (size_t)bh * SEQ * 64;
        for (int idx = tid; idx < 4096; idx += 512) {
            int jj = idx >> 4, d4 = (idx & 15) << 2;
            int pos = pos0 + jj;
            float4 v = make_float4(0.f, 0.f, 0.f, 0.f);
            if (pos >= 0) v = *(const float4*)(kbase + (size_t)pos * 64 + d4);
            *(float4*)&keys[jj * KSTRIDE + d4] = v;
        }
        __syncthreads();

        // layernorm local rows in place
        if (tid < 256) {
            int jj = tid;
            if (pos0 + jj >= 0) {
                float* rowp = &keys[jj * KSTRIDE];
                float sum = 0.f, sq = 0.f;
                #pragma unroll
                for (int d = 0; d < 64; d++) { float v = rowp[d]; sum += v; sq += v * v; }
                float mean = sum * (1.f / 64.f);
                float var  = sq * (1.f / 64.f) - mean * mean;
                float rstd = rsqrtf(var + 1e-5f);
                #pragma unroll
                for (int d = 0; d < 64; d++)
                    rowp[d] = (rowp[d] - mean) * rstd * s_lng[d] + s_lnb[d];
            }
        }
        __syncthreads();

        const int locmax  = 128 + row;
        const int locmin  = (w == 0) ? 128 : 0;
        const int locMaxW = 128 + rowMaxW;

        #pragma unroll 2
        for (int jj = locmin; jj <= locMaxW; jj++) {
            const float* kp2 = &keys[jj * KSTRIDE + d0];
            float kr[16];
            *(float4*)&kr[0]  = *(const float4*)(kp2);
            *(float4*)&kr[4]  = *(const float4*)(kp2 + 4);
            *(float4*)&kr[8]  = *(const float4*)(kp2 + 8);
            *(float4*)&kr[12] = *(const float4*)(kp2 + 12);
            float dpa = 0.f, dpb = 0.f;
            #pragma unroll
            for (int d = 0; d < 8; d++) {
                dpa += kr[d]     * qr[d];
                dpb += kr[d + 8] * qr[d + 8];
            }
            float dp = dpa + dpb;
            dp += __shfl_xor_sync(0xffffffffu, dp, 1);
            dp += __shfl_xor_sync(0xffffffffu, dp, 2);
            if (jj <= locmax) {
                float p2 = __expf(dp - FMAX);
                l += p2;
                #pragma unroll
                for (int d = 0; d < 16; d++) acc[d] += p2 * kr[d];
            }
        }
    }

    float inv = 1.f / l;
    const int b = bh >> 4, h = bh & 15;
    __half* op = out + ((size_t)b * SEQ + t) * 1024 + h * 64 + d0;
    uint32_t o[8];
    #pragma unroll
    for (int m = 0; m < 8; m++) {
        __half2 hh = __floats2half2_rn(acc[2 * m] * inv, acc[2 * m + 1] * inv);
        o[m] = *(uint32_t*)&hh;
    }
    *(uint4*)(op)     = make_uint4(o[0], o[1], o[2], o[3]);
    *(uint4*)(op + 8) = make_uint4(o[4], o[5], o[6], o[7]);
}

// ------------------------------ launcher -----------------------------------
extern "C" void kernel_launch(void* const* d_in, const int* in_sizes, int n_in,
                              void* d_out, int out_size)
{
    const float* x     = (const float*)d_in[0];
    const float* Wq    = (const float*)d_in[1];
    const float* Wkv   = (const float*)d_in[2];
    const float* Wproj = (const float*)d_in[3];
    const float* Wout  = (const float*)d_in[4];
    const float* bout  = (const float*)d_in[5];
    const float* lng   = (const float*)d_in[6];
    const float* lnb   = (const float*)d_in[7];
    const float* gng   = (const float*)d_in[8];
    const float* gnb   = (const float*)d_in[9];
    float* out = (float*)d_out;

    float *qproj, *kvproj, *qb, *kvb, *gkvb;
    __half *xh, *wqh, *wkvh, *wouth, *aouth;
    cudaGetSymbolAddress((void**)&qproj,  g_qproj);
    cudaGetSymbolAddress((void**)&kvproj, g_kvproj);
    cudaGetSymbolAddress((void**)&qb,     g_q);
    cudaGetSymbolAddress((void**)&kvb,    g_kv);
    cudaGetSymbolAddress((void**)&gkvb,   g_gkv);
    cudaGetSymbolAddress((void**)&xh,     g_xh);
    cudaGetSymbolAddress((void**)&wqh,    g_wqh);
    cudaGetSymbolAddress((void**)&wkvh,   g_wkvh);
    cudaGetSymbolAddress((void**)&wouth,  g_wouth);
    cudaGetSymbolAddress((void**)&aouth,  g_aouth);

    const int nx = NROWS * 1024, nw = 1024 * 1024;
    cvt_f2h<<<nx / (256 * 8), 256>>>(x,    xh,    nx);
    cvt_f2h<<<nw / (256 * 8), 256>>>(Wq,   wqh,   nw);
    cvt_f2h<<<nw / (256 * 8), 256>>>(Wkv,  wkvh,  nw);
    cvt_f2h<<<nw / (256 * 8), 256>>>(Wout, wouth, nw);

    dim3 gg1(1024 / 128, NROWS / 128);     // (8, 128)
    gemm_f16ldm<<<gg1, 256>>>(xh, wqh,  nullptr, qproj,  NROWS, 1024, 1024);
    gemm_f16ldm<<<gg1, 256>>>(xh, wkvh, nullptr, kvproj, NROWS, 1024, 1024);

    rotary_kernel<<<(NROWS * 512) / 256, 256>>>(qproj, kvproj, qb, kvb);

    gkv_kernel<<<dim3(NSEG, BHDIM), 32>>>(kvb, Wproj, gng, gnb, gkvb);

    int smem = 256 * KSTRIDE * sizeof(float);   // 69632 B
    cudaFuncSetAttribute(attn_kernel, cudaFuncAttributeMaxDynamicSharedMemorySize, smem);
    attn_kernel<<<dim3(NWIN, BHDIM), 512, smem>>>(qb, kvb, gkvb, lng, lnb, aouth);

    gemm_f16ldm<<<gg1, 256>>>(aouth, wouth, bout, out, NROWS, 1024, 1024);
}

// round 17
// speedup vs baseline: 1.0819x; 1.0065x over previous
#include <cuda_runtime.h>
#include <cuda_fp16.h>
#include <cstdint>

// ---------------------------------------------------------------------------
// LongShortAttention  (B=4, N=4096, DIM=1024, H=16, DH=64, W=128, S=16, R=1)
// R16: Wq/Wkv GEMMs fused into ONE N=2048 GEMM via packed [Wq|Wkv] fp16
// weight buffer (bit-identical per-element math; kills one wave tail +
// one launch).  Rest identical to R15 (1925us).
// ---------------------------------------------------------------------------

#define NROWS   16384          // B*N
#define SEQ     4096
#define NHEADS  16
#define DH      64
#define BHDIM   64             // B*HEADS
#define WIN     128
#define NWIN    32
#define NSEG    256

// -------------------- scratch (static device globals) ----------------------
__device__ float  g_qkvproj[(size_t)NROWS * 2048];  // [row][0:1024)=q, [1024:2048)=kv
__device__ float  g_q     [(size_t)NROWS * 1024];   // [bh][n][64]
__device__ float  g_kv    [(size_t)NROWS * 1024];   // [bh][n][64]
__device__ float  g_gkv   [(size_t)BHDIM * NSEG * DH];
__device__ __half g_xh    [(size_t)NROWS * 1024];
__device__ __half g_wqkvh [(size_t)1024 * 2048];    // packed [Wq | Wkv]
__device__ __half g_wouth [1024 * 1024];
__device__ __half g_aouth [(size_t)NROWS * 1024];   // [b][t][h*64+d]

// ------------------------------ helpers ------------------------------------
__device__ __forceinline__ void mma_f16(float* c, const uint32_t* a, const uint32_t* b) {
    asm volatile(
        "mma.sync.aligned.m16n8k16.row.col.f32.f16.f16.f32 "
        "{%0,%1,%2,%3}, {%4,%5,%6,%7}, {%8,%9}, {%0,%1,%2,%3};"
        : "+f"(c[0]), "+f"(c[1]), "+f"(c[2]), "+f"(c[3])
        : "r"(a[0]), "r"(a[1]), "r"(a[2]), "r"(a[3]), "r"(b[0]), "r"(b[1]));
}

__device__ __forceinline__ void ldm_x4(uint32_t* r, uint32_t addr) {
    asm volatile("ldmatrix.sync.aligned.m8n8.x4.shared.b16 {%0,%1,%2,%3}, [%4];"
        : "=r"(r[0]), "=r"(r[1]), "=r"(r[2]), "=r"(r[3]) : "r"(addr));
}

__device__ __forceinline__ void ldm_x4_t(uint32_t* r, uint32_t addr) {
    asm volatile("ldmatrix.sync.aligned.m8n8.x4.trans.shared.b16 {%0,%1,%2,%3}, [%4];"
        : "=r"(r[0]), "=r"(r[1]), "=r"(r[2]), "=r"(r[3]) : "r"(addr));
}

// ------------------------ fp32 -> fp16 conversion --------------------------
__global__ __launch_bounds__(256)
void cvt_f2h(const float* __restrict__ src, __half* __restrict__ dst, int n)
{
    int i = (blockIdx.x * blockDim.x + threadIdx.x) * 8;
    if (i >= n) return;
    float4 v0 = *(const float4*)(src + i);
    float4 v1 = *(const float4*)(src + i + 4);
    __half2 h0 = __floats2half2_rn(v0.x, v0.y);
    __half2 h1 = __floats2half2_rn(v0.z, v0.w);
    __half2 h2 = __floats2half2_rn(v1.x, v1.y);
    __half2 h3 = __floats2half2_rn(v1.z, v1.w);
    uint4 u;
    u.x = *(uint32_t*)&h0; u.y = *(uint32_t*)&h1;
    u.z = *(uint32_t*)&h2; u.w = *(uint32_t*)&h3;
    *(uint4*)(dst + i) = u;
}

// pack [Wq | Wkv] (each [1024][1024] f32, row-major) -> half [1024][2048]
__global__ __launch_bounds__(256)
void cvt_pack_qkv(const float* __restrict__ wq, const float* __restrict__ wkv,
                  __half* __restrict__ dst)
{
    int i = (blockIdx.x * blockDim.x + threadIdx.x) * 8;   // over 1024*1024
    if (i >= 1024 * 1024) return;
    int k = i >> 10, c = i & 1023;
    float4 q0 = *(const float4*)(wq  + i);
    float4 q1 = *(const float4*)(wq  + i + 4);
    float4 v0 = *(const float4*)(wkv + i);
    float4 v1 = *(const float4*)(wkv + i + 4);
    __half2 a0 = __floats2half2_rn(q0.x, q0.y);
    __half2 a1 = __floats2half2_rn(q0.z, q0.w);
    __half2 a2 = __floats2half2_rn(q1.x, q1.y);
    __half2 a3 = __floats2half2_rn(q1.z, q1.w);
    __half2 b0 = __floats2half2_rn(v0.x, v0.y);
    __half2 b1 = __floats2half2_rn(v0.z, v0.w);
    __half2 b2 = __floats2half2_rn(v1.x, v1.y);
    __half2 b3 = __floats2half2_rn(v1.z, v1.w);
    uint4 ua, ub;
    ua.x = *(uint32_t*)&a0; ua.y = *(uint32_t*)&a1;
    ua.z = *(uint32_t*)&a2; ua.w = *(uint32_t*)&a3;
    ub.x = *(uint32_t*)&b0; ub.y = *(uint32_t*)&b1;
    ub.z = *(uint32_t*)&b2; ub.w = *(uint32_t*)&b3;
    *(uint4*)(dst + (size_t)k * 2048 + c)        = ua;
    *(uint4*)(dst + (size_t)k * 2048 + 1024 + c) = ub;
}

// --------------------------- f16 tiled GEMM (R10) --------------------------
#define A_STR 80
#define B_STR 272

__global__ __launch_bounds__(256, 2)
void gemm_f16ldm(const __half* __restrict__ A, const __half* __restrict__ B,
                 const float* __restrict__ bias, float* __restrict__ C,
                 int M, int N, int K)
{
    __shared__ __align__(16) char sA[128 * A_STR];   // 10240 B
    __shared__ __align__(16) char sB[32 * B_STR];    // 8704 B

    const int tid = threadIdx.x;
    const size_t bM = (size_t)blockIdx.y * 128;
    const size_t bN = (size_t)blockIdx.x * 128;

    const __half* Ab = A + bM * (size_t)K;
    const __half* Bb = B + bN;

    const int aRow = tid >> 2;
    const int aOff = tid & 3;
    const int bRow = tid >> 4;
    const int bOff = tid & 15;

    const int wid  = tid >> 5;
    const int lane = tid & 31;
    const int wm   = wid >> 2;
    const int wn   = wid & 3;
    const int mbase = wm * 64;
    const int nbase = wn * 32;
    const int g  = lane >> 2;
    const int tg = lane & 3;
    const int part = lane >> 3;
    const int r8   = lane & 7;

    const uint32_t sA32 = (uint32_t)__cvta_generic_to_shared(sA);
    const uint32_t sB32 = (uint32_t)__cvta_generic_to_shared(sB);

    float acc[4][4][4];
    #pragma unroll
    for (int mt = 0; mt < 4; mt++)
        #pragma unroll
        for (int nt = 0; nt < 4; nt++)
            #pragma unroll
            for (int r = 0; r < 4; r++) acc[mt][nt][r] = 0.f;

    uint4 pa0 = *(const uint4*)(Ab + (size_t)aRow        * K + aOff * 8);
    uint4 pa1 = *(const uint4*)(Ab + (size_t)(aRow + 64) * K + aOff * 8);
    uint4 pb0 = *(const uint4*)(Bb + (size_t)bRow        * N + bOff * 8);
    uint4 pb1 = *(const uint4*)(Bb + (size_t)(bRow + 16) * N + bOff * 8);

    const int nKT = K / 32;
    for (int kt = 0; kt < nKT; kt++) {
        *(uint4*)(sA + aRow        * A_STR + aOff * 16) = pa0;
        *(uint4*)(sA + (aRow + 64) * A_STR + aOff * 16) = pa1;
        *(uint4*)(sB + bRow        * B_STR + bOff * 16) = pb0;
        *(uint4*)(sB + (bRow + 16) * B_STR + bOff * 16) = pb1;
        __syncthreads();

        if (kt + 1 < nKT) {
            const int k0 = (kt + 1) * 32;
            pa0 = *(const uint4*)(Ab + (size_t)aRow        * K + k0 + aOff * 8);
            pa1 = *(const uint4*)(Ab + (size_t)(aRow + 64) * K + k0 + aOff * 8);
            pb0 = *(const uint4*)(Bb + (size_t)(k0 + bRow)      * N + bOff * 8);
            pb1 = *(const uint4*)(Bb + (size_t)(k0 + bRow + 16) * N + bOff * 8);
        }

        #pragma unroll
        for (int ks = 0; ks < 2; ks++) {
            uint32_t afr[4][4], bfr[4][2];
            #pragma unroll
            for (int mt = 0; mt < 4; mt++) {
                const int row = mbase + mt * 16 + r8 + (part & 1) * 8;
                const uint32_t byte = (uint32_t)(ks * 32 + (part >> 1) * 16);
                ldm_x4(afr[mt], sA32 + row * A_STR + byte);
            }
            #pragma unroll
            for (int np = 0; np < 2; np++) {
                uint32_t t[4];
                const int row = ks * 16 + r8 + (part & 1) * 8;
                const uint32_t byte = (uint32_t)((nbase + np * 16) * 2 + (part >> 1) * 16);
                ldm_x4_t(t, sB32 + row * B_STR + byte);
                bfr[2 * np][0]     = t[0];
                bfr[2 * np][1]     = t[1];
                bfr[2 * np + 1][0] = t[2];
                bfr[2 * np + 1][1] = t[3];
            }
            #pragma unroll
            for (int mt = 0; mt < 4; mt++)
                #pragma unroll
                for (int nt = 0; nt < 4; nt++)
                    mma_f16(acc[mt][nt], afr[mt], bfr[nt]);
        }
        __syncthreads();
    }

    #pragma unroll
    for (int mt = 0; mt < 4; mt++) {
        const size_t row0 = bM + mbase + mt * 16 + g;
        #pragma unroll
        for (int nt = 0; nt < 4; nt++) {
            const size_t col = bN + nbase + nt * 8 + tg * 2;
            float bz0 = 0.f, bz1 = 0.f;
            if (bias) { bz0 = bias[col]; bz1 = bias[col + 1]; }
            float2 v0 = make_float2(acc[mt][nt][0] + bz0, acc[mt][nt][1] + bz1);
            float2 v1 = make_float2(acc[mt][nt][2] + bz0, acc[mt][nt][3] + bz1);
            *(float2*)(C + row0 * (size_t)N + col)       = v0;
            *(float2*)(C + (row0 + 8) * (size_t)N + col) = v1;
        }
    }
}

// ------------------------------- rotary ------------------------------------
// reads the fused qkvproj buffer: q at [r][h*64+i], kv at [r][1024+h*64+i]
__global__ __launch_bounds__(256)
void rotary_kernel(const float* __restrict__ qkvp,
                   float* __restrict__ qo, float* __restrict__ ko)
{
    int idx = blockIdx.x * blockDim.x + threadIdx.x;
    if (idx >= NROWS * 512) return;
    int r = idx >> 9;
    int p = idx & 511;
    int h = p >> 5;
    int i = p & 31;
    int n = r & (SEQ - 1);
    int b = r >> 12;

    float invf  = __powf(10000.f, (-2.f / 64.f) * (float)i);
    float theta = (float)n * invf;
    float s, c;
    sincosf(theta, &s, &c);

    size_t src = (size_t)r * 2048 + h * 64 + i;
    float q0 = qkvp[src],        q1 = qkvp[src + 32];
    float k0 = qkvp[src + 1024], k1 = qkvp[src + 1024 + 32];

    size_t dst = (((size_t)(b * NHEADS + h)) * SEQ + n) * 64 + i;
    const float SC = 0.125f;
    qo[dst]      = (q0 * c - q1 * s) * SC;
    qo[dst + 32] = (q1 * c + q0 * s) * SC;
    ko[dst]      = k0 * c - k1 * s;
    ko[dst + 32] = k1 * c + k0 * s;
}

// ------------------------- global kv aggregation ---------------------------
__global__ __launch_bounds__(32)
void gkv_kernel(const float* __restrict__ kv, const float* __restrict__ Wproj,
                const float* __restrict__ gg, const float* __restrict__ gb,
                float* __restrict__ gkv)
{
    __shared__ float skv[16 * 68];
    __shared__ float swp[64];
    __shared__ float slog[16];

    const int seg  = blockIdx.x;
    const int bh   = blockIdx.y;
    const int lane = threadIdx.x;

    const float* base = kv + ((size_t)bh * SEQ + seg * 16) * 64;
    for (int i = lane; i < 256; i += 32) {
        int s = i >> 4, d4 = (i & 15) << 2;
        *(float4*)&skv[s * 68 + d4] = *(const float4*)(base + s * 64 + d4);
    }
    if (lane < 16) *(float4*)&swp[lane * 4] = *(const float4*)(Wproj + lane * 4);
    __syncwarp();

    if (lane < 16) {
        float a = 0.f;
        #pragma unroll
        for (int d = 0; d < 64; d++) a += skv[lane * 68 + d] * swp[d];
        slog[lane] = a;
    }
    __syncwarp();

    float mx = -1e30f;
    #pragma unroll
    for (int s = 0; s < 16; s++) mx = fmaxf(mx, slog[s]);
    float se = 0.f;
    #pragma unroll
    for (int s = 0; s < 16; s++) se += __expf(slog[s] - mx);
    float inv = 1.f / se;

    float g0 = 0.f, g1 = 0.f;
    #pragma unroll
    for (int s = 0; s < 16; s++) {
        float ps = __expf(slog[s] - mx) * inv;
        g0 += ps * skv[s * 68 + lane];
        g1 += ps * skv[s * 68 + lane + 32];
    }

    float sum = g0 + g1, sq = g0 * g0 + g1 * g1;
    #pragma unroll
    for (int o = 16; o; o >>= 1) {
        sum += __shfl_xor_sync(0xffffffffu, sum, o);
        sq  += __shfl_xor_sync(0xffffffffu, sq, o);
    }
    float mean = sum * (1.f / 64.f);
    float var  = sq * (1.f / 64.f) - mean * mean;
    float rstd = rsqrtf(var + 1e-5f);

    float* outp = gkv + ((size_t)bh * NSEG + seg) * 64;
    outp[lane]      = (g0 - mean) * rstd * gg[lane]      + gb[lane];
    outp[lane + 32] = (g1 - mean) * rstd * gg[lane + 32] + gb[lane + 32];
}

// ------------------------------ attention ----------------------------------
#define KSTRIDE 68
#define FMAX 16.0f

__global__ __launch_bounds__(512, 2)
void attn_kernel(const float* __restrict__ q, const float* __restrict__ kv,
                 const float* __restrict__ gkv, const float* __restrict__ lng_,
                 const float* __restrict__ lnb_, __half* __restrict__ out)
{
    extern __shared__ float keys[];     // [256][KSTRIDE]
    __shared__ float s_lng[64], s_lnb[64];

    const int w   = blockIdx.x;
    const int bh  = blockIdx.y;
    const int tid = threadIdx.x;

    if (tid < 64)  { s_lng[tid] = lng_[tid]; s_lnb[tid] = lnb_[tid]; }

    const int row  = tid >> 2;
    const int quad = tid & 3;
    const int t    = w * WIN + row;
    const int d0   = quad * 16;

    const int warpid  = tid >> 5;
    const int rowMaxW = warpid * 8 + 7;

    float qr[16], acc[16];
    const float* qp = q + ((size_t)bh * SEQ + t) * 64 + d0;
    #pragma unroll
    for (int m = 0; m < 4; m++) *(float4*)&qr[m * 4] = *(const float4*)(qp + m * 4);
    #pragma unroll
    for (int d = 0; d < 16; d++) acc[d] = 0.f;
    float l = 0.f;

    // ======================= phase A: global keys =========================
    {
        const float* gbase = gkv + (size_t)bh * NSEG * 64;
        for (int idx = tid; idx < 4096; idx += 512) {
            int j = idx >> 4, d4 = (idx & 15) << 2;
            *(float4*)&keys[j * KSTRIDE + d4] = *(const float4*)(gbase + j * 64 + d4);
        }
        __syncthreads();

        const int nglobal = t >> 4;
        const int gLimW   = min(NSEG, (w * WIN + rowMaxW) >> 4);

        #pragma unroll 2
        for (int j = 0; j < gLimW; j++) {
            const float* kp2 = &keys[j * KSTRIDE + d0];
            float kr[16];
            *(float4*)&kr[0]  = *(const float4*)(kp2);
            *(float4*)&kr[4]  = *(const float4*)(kp2 + 4);
            *(float4*)&kr[8]  = *(const float4*)(kp2 + 8);
            *(float4*)&kr[12] = *(const float4*)(kp2 + 12);
            float dpa = 0.f, dpb = 0.f;
            #pragma unroll
            for (int d = 0; d < 8; d++) {
                dpa += kr[d]     * qr[d];
                dpb += kr[d + 8] * qr[d + 8];
            }
            float dp = dpa + dpb;
            dp += __shfl_xor_sync(0xffffffffu, dp, 1);
            dp += __shfl_xor_sync(0xffffffffu, dp, 2);
            if (j < nglobal) {
                float p2 = __expf(dp - FMAX);
                l += p2;
                #pragma unroll
                for (int d = 0; d < 16; d++) acc[d] += p2 * kr[d];
            }
        }
        __syncthreads();   // everyone done reading global keys
    }

    // ======================= phase B: local keys ==========================
    {
        const int pos0 = (w - 1) * WIN;
        const float* kbase = kv + (size_t)bh * SEQ * 64;
        for (int idx = tid; idx < 4096; idx += 512) {
            int jj = idx >> 4, d4 = (idx & 15) << 2;
            int pos = pos0 + jj;
            float4 v = make_float4(0.f, 0.f, 0.f, 0.f);
            if (pos >= 0) v = *(const float4*)(kbase + (size_t)pos * 64 + d4);
            *(float4*)&keys[jj * KSTRIDE + d4] = v;
        }
        __syncthreads();

        if (tid < 256) {
            int jj = tid;
            if (pos0 + jj >= 0) {
                float* rowp = &keys[jj * KSTRIDE];
                float sum = 0.f, sq = 0.f;
                #pragma unroll
                for (int d = 0; d < 64; d++) { float v = rowp[d]; sum += v; sq += v * v; }
                float mean = sum * (1.f / 64.f);
                float var  = sq * (1.f / 64.f) - mean * mean;
                float rstd = rsqrtf(var + 1e-5f);
                #pragma unroll
                for (int d = 0; d < 64; d++)
                    rowp[d] = (rowp[d] - mean) * rstd * s_lng[d] + s_lnb[d];
            }
        }
        __syncthreads();

        const int locmax  = 128 + row;
        const int locmin  = (w == 0) ? 128 : 0;
        const int locMaxW = 128 + rowMaxW;

        #pragma unroll 2
        for (int jj = locmin; jj <= locMaxW; jj++) {
            const float* kp2 = &keys[jj * KSTRIDE + d0];
            float kr[16];
            *(float4*)&kr[0]  = *(const float4*)(kp2);
            *(float4*)&kr[4]  = *(const float4*)(kp2 + 4);
            *(float4*)&kr[8]  = *(const float4*)(kp2 + 8);
            *(float4*)&kr[12] = *(const float4*)(kp2 + 12);
            float dpa = 0.f, dpb = 0.f;
            #pragma unroll
            for (int d = 0; d < 8; d++) {
                dpa += kr[d]     * qr[d];
                dpb += kr[d + 8] * qr[d + 8];
            }
            float dp = dpa + dpb;
            dp += __shfl_xor_sync(0xffffffffu, dp, 1);
            dp += __shfl_xor_sync(0xffffffffu, dp, 2);
            if (jj <= locmax) {
                float p2 = __expf(dp - FMAX);
                l += p2;
                #pragma unroll
                for (int d = 0; d < 16; d++) acc[d] += p2 * kr[d];
            }
        }
    }

    float inv = 1.f / l;
    const int b = bh >> 4, h = bh & 15;
    __half* op = out + ((size_t)b * SEQ + t) * 1024 + h * 64 + d0;
    uint32_t o[8];
    #pragma unroll
    for (int m = 0; m < 8; m++) {
        __half2 hh = __floats2half2_rn(acc[2 * m] * inv, acc[2 * m + 1] * inv);
        o[m] = *(uint32_t*)&hh;
    }
    *(uint4*)(op)     = make_uint4(o[0], o[1], o[2], o[3]);
    *(uint4*)(op + 8) = make_uint4(o[4], o[5], o[6], o[7]);
}

// ------------------------------ launcher -----------------------------------
extern "C" void kernel_launch(void* const* d_in, const int* in_sizes, int n_in,
                              void* d_out, int out_size)
{
    const float* x     = (const float*)d_in[0];
    const float* Wq    = (const float*)d_in[1];
    const float* Wkv   = (const float*)d_in[2];
    const float* Wproj = (const float*)d_in[3];
    const float* Wout  = (const float*)d_in[4];
    const float* bout  = (const float*)d_in[5];
    const float* lng   = (const float*)d_in[6];
    const float* lnb   = (const float*)d_in[7];
    const float* gng   = (const float*)d_in[8];
    const float* gnb   = (const float*)d_in[9];
    float* out = (float*)d_out;

    float *qkvproj, *qb, *kvb, *gkvb;
    __half *xh, *wqkvh, *wouth, *aouth;
    cudaGetSymbolAddress((void**)&qkvproj, g_qkvproj);
    cudaGetSymbolAddress((void**)&qb,      g_q);
    cudaGetSymbolAddress((void**)&kvb,     g_kv);
    cudaGetSymbolAddress((void**)&gkvb,    g_gkv);
    cudaGetSymbolAddress((void**)&xh,      g_xh);
    cudaGetSymbolAddress((void**)&wqkvh,   g_wqkvh);
    cudaGetSymbolAddress((void**)&wouth,   g_wouth);
    cudaGetSymbolAddress((void**)&aouth,   g_aouth);

    const int nx = NROWS * 1024, nw = 1024 * 1024;
    cvt_f2h<<<nx / (256 * 8), 256>>>(x,    xh,    nx);
    cvt_pack_qkv<<<nw / (256 * 8), 256>>>(Wq, Wkv, wqkvh);
    cvt_f2h<<<nw / (256 * 8), 256>>>(Wout, wouth, nw);

    // fused q/kv projection: one GEMM, N = 2048
    dim3 gqkv(2048 / 128, NROWS / 128);    // (16, 128)
    gemm_f16ldm<<<gqkv, 256>>>(xh, wqkvh, nullptr, qkvproj, NROWS, 2048, 1024);

    rotary_kernel<<<(NROWS * 512) / 256, 256>>>(qkvproj, qb, kvb);

    gkv_kernel<<<dim3(NSEG, BHDIM), 32>>>(kvb, Wproj, gng, gnb, gkvb);

    int smem = 256 * KSTRIDE * sizeof(float);   // 69632 B
    cudaFuncSetAttribute(attn_kernel, cudaFuncAttributeMaxDynamicSharedMemorySize, smem);
    attn_kernel<<<dim3(NWIN, BHDIM), 512, smem>>>(qb, kvb, gkvb, lng, lnb, aouth);

    dim3 gout(1024 / 128, NROWS / 128);    // (8, 128)
    gemm_f16ldm<<<gout, 256>>>(aouth, wouth, bout, out, NROWS, 1024, 1024);
}